// round 3
// baseline (speedup 1.0000x reference)
#include <cuda_runtime.h>

#define B_ 4
#define N_ 512
#define F_ 64
#define R_ 128
#define PAIRS 511                 // N-1
#define P_TOT (N_ * PAIRS)        // 261632
#define TQ 128                    // j-rows per block
#define STR 132                   // padded smem row stride (floats), 132*4 % 16 == 0

// Precomputed half-GEMMs: A = feat @ W1[:64] + b1, Bv = feat @ W1[64:]
__device__ float4 g_Abuf[B_ * N_ * R_ / 4];
__device__ float4 g_Bbuf[B_ * N_ * R_ / 4];

// ---------------------------------------------------------------------------
// packed fp32x2 helpers (sm_100+)
// ---------------------------------------------------------------------------
__device__ __forceinline__ void ffma2(unsigned long long& d,
                                      unsigned long long a,
                                      unsigned long long b) {
    asm("fma.rn.f32x2 %0, %1, %2, %0;" : "+l"(d) : "l"(a), "l"(b));
}
__device__ __forceinline__ unsigned long long pack2(float x) {
    unsigned long long r;
    asm("mov.b64 %0, {%1, %1};" : "=l"(r) : "f"(x));
    return r;
}
__device__ __forceinline__ void unpack2(unsigned long long v, float& lo, float& hi) {
    asm("mov.b64 {%0, %1}, %2;" : "=f"(lo), "=f"(hi) : "l"(v));
}

// ---------------------------------------------------------------------------
// Kernel 1: per-(b,n) half-projections. Grid = B*N blocks, 128 threads (r).
// ---------------------------------------------------------------------------
__global__ __launch_bounds__(128) void precompute_kernel(
    const float* __restrict__ feat, const float* __restrict__ W1,
    const float* __restrict__ b1) {
    __shared__ float sf[F_];
    const int bn = blockIdx.x;
    const int r = threadIdx.x;
    if (r < F_) sf[r] = feat[bn * F_ + r];
    __syncthreads();
    float a = b1[r];
    float bb = 0.f;
#pragma unroll 8
    for (int f = 0; f < F_; ++f) {
        float fv = sf[f];
        a  += fv * W1[f * R_ + r];
        bb += fv * W1[(F_ + f) * R_ + r];
    }
    ((float*)g_Abuf)[bn * R_ + r] = a;
    ((float*)g_Bbuf)[bn * R_ + r] = bb;
}

// ---------------------------------------------------------------------------
// Kernel 2: fused pair-MLP. Block = (b, i, 128-row j-tile).
// 256 threads = 16(tx: col groups) x 16(ty: row groups); thread tile 8x8.
// ---------------------------------------------------------------------------
extern __shared__ float smem[];

__global__ __launch_bounds__(256, 1) void relnet_main(
    const float* __restrict__ W2, const float* __restrict__ b2,
    const float* __restrict__ W3, const float* __restrict__ b3,
    float* __restrict__ out) {
    float* sW2  = smem;                 // 128 * 132
    float* sH1  = smem + 128 * STR;     // 128 * 132
    float* sAi  = sH1 + 128 * STR;      // 128
    float* sRed = sAi + 128;            // 128 * 16

    const int jt = blockIdx.x;
    const int i  = blockIdx.y;
    const int b  = blockIdx.z;
    const int tid = threadIdx.x;
    const int tx = tid & 15;
    const int ty = tid >> 4;

    // A row for this i (b1 already folded in)
    if (tid < 32) ((float4*)sAi)[tid] = g_Abuf[(b * N_ + i) * 32 + tid];

    // Stage W2 into smem (row-major, padded). Coalesced float4.
    const float4* W2v = (const float4*)W2;
#pragma unroll
    for (int it = 0; it < 16; ++it) {
        int v = tid + it * 256;
        int k = v >> 5, c = v & 31;
        *(float4*)(sW2 + k * STR + c * 4) = W2v[v];
    }
    __syncthreads();

    // Build h1 tile: h1[q][k] = relu(A[i][k] + Bv[j(q)][k]), row-major in smem.
    const float4* Bb = g_Bbuf + (size_t)b * N_ * 32;
#pragma unroll
    for (int it = 0; it < 16; ++it) {
        int v = tid + it * 256;
        int q = v >> 5, kv = v & 31;
        int qg = jt * TQ + q;
        if (qg > PAIRS - 1) qg = PAIRS - 1;       // clamp tail (row recomputed, not written)
        int j = qg + (qg >= i);
        float4 bv = Bb[j * 32 + kv];
        float4 av = ((const float4*)sAi)[kv];
        float4 h;
        h.x = fmaxf(av.x + bv.x, 0.f);
        h.y = fmaxf(av.y + bv.y, 0.f);
        h.z = fmaxf(av.z + bv.z, 0.f);
        h.w = fmaxf(av.w + bv.w, 0.f);
        *(float4*)(sH1 + q * STR + kv * 4) = h;
    }
    __syncthreads();

    // Mainloop: 8x8 register tile, f32x2-packed accumulators (pairs of cols).
    unsigned long long acc[8][4];
#pragma unroll
    for (int r = 0; r < 8; ++r)
#pragma unroll
        for (int p = 0; p < 4; ++p) acc[r][p] = 0ull;

    const float* h1p = sH1 + (ty * 8) * STR;
    const float* w2p = sW2 + tx * 8;

#pragma unroll 2
    for (int k4 = 0; k4 < R_; k4 += 4) {
        float4 av[8];
#pragma unroll
        for (int r = 0; r < 8; ++r)
            av[r] = *(const float4*)(h1p + r * STR + k4);
#pragma unroll
        for (int kk = 0; kk < 4; ++kk) {
            const float* wrow = w2p + (k4 + kk) * STR;
            ulonglong2 w0 = *(const ulonglong2*)(wrow);
            ulonglong2 w1 = *(const ulonglong2*)(wrow + 4);
#pragma unroll
            for (int r = 0; r < 8; ++r) {
                float s = ((const float*)&av[r])[kk];
                unsigned long long a2 = pack2(s);
                ffma2(acc[r][0], a2, w0.x);
                ffma2(acc[r][1], a2, w0.y);
                ffma2(acc[r][2], a2, w1.x);
                ffma2(acc[r][3], a2, w1.y);
            }
        }
    }

    // Epilogue: +b2, relu, dot with W3 columns owned by this thread.
    float b2v[8], w3v[8];
#pragma unroll
    for (int c = 0; c < 8; ++c) {
        b2v[c] = b2[tx * 8 + c];
        w3v[c] = W3[tx * 8 + c];
    }

    float part[8];
#pragma unroll
    for (int r = 0; r < 8; ++r) {
        float s = 0.f;
#pragma unroll
        for (int p = 0; p < 4; ++p) {
            float lo, hi;
            unpack2(acc[r][p], lo, hi);
            s += fmaxf(lo + b2v[p * 2 + 0], 0.f) * w3v[p * 2 + 0];
            s += fmaxf(hi + b2v[p * 2 + 1], 0.f) * w3v[p * 2 + 1];
        }
        part[r] = s;
    }
#pragma unroll
    for (int r = 0; r < 8; ++r) sRed[(ty * 8 + r) * 16 + tx] = part[r];
    __syncthreads();

    if (tid < 128) {
        float s = 0.f;
#pragma unroll
        for (int t = 0; t < 16; ++t) s += sRed[tid * 16 + t];
        s += b3[0];
        int qg = jt * TQ + tid;
        if (qg < PAIRS)
            out[(size_t)b * P_TOT + (size_t)i * PAIRS + qg] = s;
    }
}

// ---------------------------------------------------------------------------
extern "C" void kernel_launch(void* const* d_in, const int* in_sizes, int n_in,
                              void* d_out, int out_size) {
    const float* feat = (const float*)d_in[0];
    const float* W1   = (const float*)d_in[1];
    const float* b1   = (const float*)d_in[2];
    const float* W2   = (const float*)d_in[3];
    const float* b2   = (const float*)d_in[4];
    const float* W3   = (const float*)d_in[5];
    const float* b3   = (const float*)d_in[6];
    float* out = (float*)d_out;

    precompute_kernel<<<B_ * N_, 128>>>(feat, W1, b1);

    const size_t shbytes = (size_t)(128 * STR * 2 + 128 + 128 * 16) * sizeof(float); // 143872
    cudaFuncSetAttribute(relnet_main, cudaFuncAttributeMaxDynamicSharedMemorySize,
                         (int)shbytes);
    dim3 grid(4, N_, B_);
    relnet_main<<<grid, 256, shbytes>>>(W2, b2, W3, b3, out);
}

// round 8
// speedup vs baseline: 2.6642x; 2.6642x over previous
#include <cuda_runtime.h>
#include <cstdint>

#define B_ 4
#define N_ 512
#define F_ 64
#define R_ 128
#define PAIRS 511                 // N-1
#define P_TOT (N_ * PAIRS)        // 261632
#define GI 8                      // i-values per CTA

// Precomputed half-GEMMs in PAIR-PERMUTED column order:
// column r=ks*8+kk  ->  pos = ks*8 + (kk&3)*2 + (kk>>2)
// so that (k, k+4) live in one aligned float2 (matches tf32 mma fragments).
__device__ float g_Abuf[B_ * N_ * R_];   // A = feat @ W1[:64] + b1
__device__ float g_Bbuf[B_ * N_ * R_];   // Bv = feat @ W1[64:]
// W2 tf32-rounded, fragment layout: W2p[(ks*4+t)][n] = (W2[ks*8+t][n], W2[ks*8+t+4][n])
// row stride 132 float2 (bank-staggered).
__device__ float g_W2t[64 * 132 * 2];

__device__ __forceinline__ float t32(float x) {
    float r;
    asm("cvt.rna.tf32.f32 %0, %1;" : "=f"(r) : "f"(x));
    return r;
}

__device__ __forceinline__ void mma_tf32(float* d, uint32_t a0, uint32_t a1,
                                         uint32_t a2, uint32_t a3,
                                         uint32_t b0, uint32_t b1) {
    asm volatile(
        "mma.sync.aligned.m16n8k8.row.col.f32.tf32.tf32.f32 "
        "{%0,%1,%2,%3}, {%4,%5,%6,%7}, {%8,%9}, {%0,%1,%2,%3};"
        : "+f"(d[0]), "+f"(d[1]), "+f"(d[2]), "+f"(d[3])
        : "r"(a0), "r"(a1), "r"(a2), "r"(a3), "r"(b0), "r"(b1));
}

// ---------------------------------------------------------------------------
// Kernel 1: per-(b,n) half-projections, stored pair-permuted.
// ---------------------------------------------------------------------------
__global__ __launch_bounds__(128) void precompute_kernel(
    const float* __restrict__ feat, const float* __restrict__ W1,
    const float* __restrict__ b1) {
    __shared__ float sf[F_];
    const int bn = blockIdx.x;
    const int r = threadIdx.x;
    if (r < F_) sf[r] = feat[bn * F_ + r];
    __syncthreads();
    float a = b1[r];
    float bb = 0.f;
#pragma unroll 8
    for (int f = 0; f < F_; ++f) {
        float fv = sf[f];
        a  += fv * W1[f * R_ + r];
        bb += fv * W1[(F_ + f) * R_ + r];
    }
    int pos = (r & ~7) | ((r & 3) << 1) | ((r >> 2) & 1);
    g_Abuf[bn * R_ + pos] = a;
    g_Bbuf[bn * R_ + pos] = bb;
}

// Kernel 1b: W2 -> tf32, fragment-permuted image.
__global__ __launch_bounds__(256) void w2t_kernel(const float* __restrict__ W2) {
    const int tid = threadIdx.x;
#pragma unroll
    for (int it = 0; it < 64; ++it) {
        int idx = it * 256 + tid;          // idx = k*128 + n
        int k = idx >> 7, n = idx & 127;
        float v = t32(W2[idx]);
        int ks = k >> 3, kk = k & 7, tq = kk & 3, hi = kk >> 2;
        g_W2t[((ks * 4 + tq) * 132 + n) * 2 + hi] = v;
    }
}

// ---------------------------------------------------------------------------
// Kernel 2: HMMA tf32 fused pair-MLP.
// Grid (4 jt, 64 ig, 4 b), 256 threads = 8 warps.
// Warp w: qh = w&1 (64-row q half), nq = w>>1 (32-col quarter).
// SMEM: W2p 67584 | h1 128 rows x 544B | Bv slab 129x512B | red 128x4 f32
// ---------------------------------------------------------------------------
#define OFF_W2 0
#define OFF_H1 67584
#define OFF_BV (67584 + 69632)          // 137216
#define OFF_RED (OFF_BV + 66048)        // 203264
#define SMEM_BYTES (OFF_RED + 2048 + 128)

extern __shared__ char smem_raw[];

__global__ __launch_bounds__(256, 1)
void relnet_mma(const float* __restrict__ b2, const float* __restrict__ W3,
                const float* __restrict__ b3, float* __restrict__ out) {
    const int tid = threadIdx.x;
    const int warp = tid >> 5;
    const int lane = tid & 31;
    const int g = lane >> 2;            // groupID
    const int t = lane & 3;             // thread-in-group
    const int qh = warp & 1;
    const int nq = warp >> 1;
    const int jt = blockIdx.x;
    const int i0 = blockIdx.y * GI;
    const int b = blockIdx.z;
    const int qbase = jt * 128;
    const int j0 = jt * 128;

    char* base = smem_raw;
    float* sBv = (float*)(base + OFF_BV);
    float* sRed = (float*)(base + OFF_RED);

    // ---- stage W2p (already permuted + tf32 in gmem) ----
    {
        const float4* src = (const float4*)g_W2t;
        float4* dst = (float4*)(base + OFF_W2);
#pragma unroll
        for (int it = 0; it < 17; ++it) {
            int v = tid + it * 256;
            if (v < 4224) dst[v] = src[v];
        }
    }
    // ---- stage Bv slab rows j0..j0+128 (129 rows, zero-pad OOB) ----
    {
        const float4* src = ((const float4*)g_Bbuf) + ((size_t)b * N_ + j0) * 32;
        float4* dst = (float4*)sBv;
        int limit = (N_ - j0 < 129 ? N_ - j0 : 129) * 32;
#pragma unroll
        for (int it = 0; it < 17; ++it) {
            int v = tid + it * 256;
            if (v < 129 * 32)
                dst[v] = (v < limit) ? src[v] : make_float4(0.f, 0.f, 0.f, 0.f);
        }
    }
    // RACE FIX (R7): first build iteration reads sBv written by other
    // threads — must barrier after staging before anyone reads it.
    __syncthreads();

    // ---- per-thread epilogue constants ----
    float b2v[4][2], w3v[4][2];
#pragma unroll
    for (int nt = 0; nt < 4; ++nt) {
        int n = nq * 32 + nt * 8 + 2 * t;
        b2v[nt][0] = b2[n];     b2v[nt][1] = b2[n + 1];
        w3v[nt][0] = W3[n];     w3v[nt][1] = W3[n + 1];
    }
    const float b3v = b3[0];

    // build-loop constants
    const int c = tid & 63;             // column-pair index 0..63
    const int q0 = tid >> 6;            // q start 0..3

    // mainloop base pointers
    const char* pA0 = base + OFF_H1 + (qh * 64 + g) * 544 + t * 8;
    const char* pB0 = base + OFF_W2 + (t * 132 + nq * 32 + g) * 8;

    for (int ti = 0; ti < GI; ++ti) {
        const int i = i0 + ti;

        // ---- build h1 tile (relu(Ai + Bv_j), tf32) into fragment layout ----
        float2 ai = *(const float2*)(g_Abuf + ((size_t)b * N_ + i) * R_ + c * 2);
#pragma unroll 8
        for (int it = 0; it < 32; ++it) {
            int q = q0 + it * 4;
            int qg = qbase + q;
            int jl = q + ((qg >= i && qg <= PAIRS - 1) ? 1 : 0);
            float2 bv = *(const float2*)(sBv + jl * 128 + c * 2);
            float2 h;
            h.x = t32(fmaxf(ai.x + bv.x, 0.f));
            h.y = t32(fmaxf(ai.y + bv.y, 0.f));
            *(float2*)(base + OFF_H1 + q * 544 + c * 8) = h;
        }
        __syncthreads();

        // ---- HMMA mainloop: 64q x 32n per warp, K=128 ----
        float d[4][4][4];
#pragma unroll
        for (int mt = 0; mt < 4; ++mt)
#pragma unroll
            for (int nt = 0; nt < 4; ++nt)
#pragma unroll
                for (int e = 0; e < 4; ++e) d[mt][nt][e] = 0.f;

#pragma unroll 4
        for (int ks = 0; ks < 16; ++ks) {
            uint2 aF[4][2];
#pragma unroll
            for (int mt = 0; mt < 4; ++mt) {
                aF[mt][0] = *(const uint2*)(pA0 + mt * 16 * 544 + ks * 32);
                aF[mt][1] = *(const uint2*)(pA0 + (mt * 16 + 8) * 544 + ks * 32);
            }
            uint2 bF[4];
#pragma unroll
            for (int nt = 0; nt < 4; ++nt)
                bF[nt] = *(const uint2*)(pB0 + ks * 4224 + nt * 64);
#pragma unroll
            for (int mt = 0; mt < 4; ++mt)
#pragma unroll
                for (int nt = 0; nt < 4; ++nt)
                    mma_tf32(d[mt][nt],
                             aF[mt][0].x, aF[mt][1].x, aF[mt][0].y, aF[mt][1].y,
                             bF[nt].x, bF[nt].y);
        }

        // ---- epilogue: relu(+b2) dot W3, quad shuffle, 4-warp reduce ----
        float p[8];
#pragma unroll
        for (int mt = 0; mt < 4; ++mt) {
            float s0 = 0.f, s1 = 0.f;
#pragma unroll
            for (int nt = 0; nt < 4; ++nt) {
                s0 += fmaxf(d[mt][nt][0] + b2v[nt][0], 0.f) * w3v[nt][0];
                s0 += fmaxf(d[mt][nt][1] + b2v[nt][1], 0.f) * w3v[nt][1];
                s1 += fmaxf(d[mt][nt][2] + b2v[nt][0], 0.f) * w3v[nt][0];
                s1 += fmaxf(d[mt][nt][3] + b2v[nt][1], 0.f) * w3v[nt][1];
            }
            p[mt * 2] = s0;
            p[mt * 2 + 1] = s1;
        }
#pragma unroll
        for (int v = 0; v < 8; ++v) {
            p[v] += __shfl_xor_sync(0xffffffffu, p[v], 1);
            p[v] += __shfl_xor_sync(0xffffffffu, p[v], 2);
        }
        // lane (g,t) writes rows of m-tile mt = t
        {
            int r0 = qh * 64 + t * 16 + g;
            sRed[r0 * 4 + nq] = p[t * 2];
            sRed[(r0 + 8) * 4 + nq] = p[t * 2 + 1];
        }
        __syncthreads();

        if (tid < 128) {
            int qg = qbase + tid;
            if (qg < PAIRS) {
                float4 rr = *(const float4*)(sRed + tid * 4);
                out[(size_t)b * P_TOT + (size_t)i * PAIRS + qg] =
                    rr.x + rr.y + rr.z + rr.w + b3v;
            }
        }
        // next iteration's build starts with its own sync after writing h1;
        // red reads above complete before the next epilogue writes (ordered by
        // the build-side __syncthreads of iteration ti+1).
    }
}

// ---------------------------------------------------------------------------
extern "C" void kernel_launch(void* const* d_in, const int* in_sizes, int n_in,
                              void* d_out, int out_size) {
    const float* feat = (const float*)d_in[0];
    const float* W1   = (const float*)d_in[1];
    const float* b1   = (const float*)d_in[2];
    const float* W2   = (const float*)d_in[3];
    const float* b2   = (const float*)d_in[4];
    const float* W3   = (const float*)d_in[5];
    const float* b3   = (const float*)d_in[6];
    float* out = (float*)d_out;

    precompute_kernel<<<B_ * N_, 128>>>(feat, W1, b1);
    w2t_kernel<<<1, 256>>>(W2);

    cudaFuncSetAttribute(relnet_mma, cudaFuncAttributeMaxDynamicSharedMemorySize,
                         SMEM_BYTES);
    dim3 grid(4, N_ / GI, B_);
    relnet_mma<<<grid, 256, SMEM_BYTES>>>(b2, W3, b3, out);
}

// round 9
// speedup vs baseline: 2.7742x; 1.0413x over previous
#include <cuda_runtime.h>
#include <cstdint>

#define B_ 4
#define N_ 512
#define F_ 64
#define R_ 128
#define PAIRS 511                 // N-1
#define P_TOT (N_ * PAIRS)        // 261632
#define GI 8                      // i-values per CTA (4 macro pairs)

// Precomputed half-GEMMs in PAIR-PERMUTED column order:
// column r=ks*8+kk -> pos = ks*8 + (kk&3)*2 + (kk>>2)  ((k,k+4) adjacent float2)
__device__ float g_Abuf[B_ * N_ * R_];   // A = feat @ W1[:64] + b1
__device__ float g_Bbuf[B_ * N_ * R_];   // Bv = feat @ W1[64:]
// W2 tf32, fragment layout: W2p[(ks*4+t)][n] = (W2[ks*8+t][n], W2[ks*8+t+4][n]),
// row stride 132 float2.
__device__ float g_W2t[64 * 132 * 2];

__device__ __forceinline__ float t32(float x) {
    float r;
    asm("cvt.rna.tf32.f32 %0, %1;" : "=f"(r) : "f"(x));
    return r;
}

__device__ __forceinline__ void mma_tf32(float* d, uint32_t a0, uint32_t a1,
                                         uint32_t a2, uint32_t a3,
                                         uint32_t b0, uint32_t b1) {
    asm volatile(
        "mma.sync.aligned.m16n8k8.row.col.f32.tf32.tf32.f32 "
        "{%0,%1,%2,%3}, {%4,%5,%6,%7}, {%8,%9}, {%0,%1,%2,%3};"
        : "+f"(d[0]), "+f"(d[1]), "+f"(d[2]), "+f"(d[3])
        : "r"(a0), "r"(a1), "r"(a2), "r"(a3), "r"(b0), "r"(b1));
}

// ---------------------------------------------------------------------------
// Prep: blocks [0,2048) = half-projections; blocks [2048,2056) = W2 permute.
// ---------------------------------------------------------------------------
__global__ __launch_bounds__(128) void prep_kernel(
    const float* __restrict__ feat, const float* __restrict__ W1,
    const float* __restrict__ b1, const float* __restrict__ W2) {
    const int blk = blockIdx.x;
    if (blk < B_ * N_) {
        __shared__ float sf[F_];
        const int r = threadIdx.x;
        if (r < F_) sf[r] = feat[blk * F_ + r];
        __syncthreads();
        float a = b1[r];
        float bb = 0.f;
#pragma unroll 8
        for (int f = 0; f < F_; ++f) {
            float fv = sf[f];
            a  += fv * W1[f * R_ + r];
            bb += fv * W1[(F_ + f) * R_ + r];
        }
        int pos = (r & ~7) | ((r & 3) << 1) | ((r >> 2) & 1);
        g_Abuf[blk * R_ + pos] = a;
        g_Bbuf[blk * R_ + pos] = bb;
    } else {
        const int base = (blk - B_ * N_) * 2048 + threadIdx.x;
#pragma unroll
        for (int it = 0; it < 16; ++it) {
            int idx = base + it * 128;       // idx = k*128 + n
            int k = idx >> 7, n = idx & 127;
            float v = t32(W2[idx]);
            int ks = k >> 3, kk = k & 7, tq = kk & 3, hi = kk >> 2;
            g_W2t[((ks * 4 + tq) * 132 + n) * 2 + hi] = v;
        }
    }
}

// ---------------------------------------------------------------------------
// Main: HMMA tf32 fused pair-MLP, 256x128 macro-tile (2 i per pass).
// Grid (4 jt, 64 ig, 4 b), 256 threads = 8 warps.
// Warp w: mq = w&3 (64-row block of 256), nh = w>>2 (64-col half).
// SMEM: W2p 67584 | h1A 128x544 | h1B 128x544 | red 256x2 f32
// ---------------------------------------------------------------------------
#define OFF_W2 0
#define OFF_H1A 67584
#define OFF_H1B (67584 + 69632)          // 137216
#define OFF_RED (OFF_H1B + 69632)        // 206848
#define SMEM_BYTES (OFF_RED + 2048 + 64)

extern __shared__ char smem_raw[];

__global__ __launch_bounds__(256, 1)
void relnet_mma(const float* __restrict__ b2, const float* __restrict__ W3,
                const float* __restrict__ b3, float* __restrict__ out) {
    const int tid = threadIdx.x;
    const int warp = tid >> 5;
    const int lane = tid & 31;
    const int g = lane >> 2;            // groupID
    const int t = lane & 3;             // thread-in-group
    const int mq = warp & 3;            // 64-row block (0,1 -> tile A; 2,3 -> tile B)
    const int nh = warp >> 2;           // 64-col half
    const int jt = blockIdx.x;
    const int i0 = blockIdx.y * GI;
    const int b = blockIdx.z;
    const int qbase = jt * 128;
    const int j0 = jt * 128;

    char* base = smem_raw;
    float* sRed = (float*)(base + OFF_RED);

    // ---- stage W2p (already permuted + tf32 in gmem) ----
    {
        const float4* src = (const float4*)g_W2t;
        float4* dst = (float4*)(base + OFF_W2);
#pragma unroll
        for (int it = 0; it < 17; ++it) {
            int v = tid + it * 256;
            if (v < 4224) dst[v] = src[v];
        }
    }

    // ---- per-thread epilogue constants (64 n per warp) ----
    float b2v[8][2], w3v[8][2];
#pragma unroll
    for (int nt = 0; nt < 8; ++nt) {
        int n = nh * 64 + nt * 8 + 2 * t;
        b2v[nt][0] = b2[n];     b2v[nt][1] = b2[n + 1];
        w3v[nt][0] = W3[n];     w3v[nt][1] = W3[n + 1];
    }
    const float b3v = b3[0];

    // build-loop constants
    const int c = tid & 63;             // column-pair index 0..63
    const int q0 = tid >> 6;            // q start 0..3
    const float* BvBase = g_Bbuf + ((size_t)b * N_ + j0) * R_;

    // mainloop base pointers
    const char* pA0 = base + (mq >= 2 ? OFF_H1B : OFF_H1A) +
                      ((mq & 1) * 64 + g) * 544 + t * 8;
    const char* pB0 = base + OFF_W2 + (t * 132 + nh * 64 + g) * 8;

    __syncthreads();   // W2p staged before first mainloop

    for (int m = 0; m < 4; ++m) {
        const int ia = i0 + 2 * m;
        const int ib = ia + 1;

        // ---- build h1A/h1B (relu(Ai + Bv_j), tf32); Bv straight from L2 ----
        float2 aiA = *(const float2*)(g_Abuf + ((size_t)b * N_ + ia) * R_ + c * 2);
        float2 aiB = *(const float2*)(g_Abuf + ((size_t)b * N_ + ib) * R_ + c * 2);
#pragma unroll 4
        for (int it = 0; it < 32; ++it) {
            int q = q0 + it * 4;
            int qg = qbase + q;
            int jlA = q + ((qg >= ia && qg <= PAIRS - 1) ? 1 : 0);
            int jlB = q + ((qg >= ib && qg <= PAIRS - 1) ? 1 : 0);
            float2 bvA = *(const float2*)(BvBase + jlA * R_ + c * 2);
            float2 bvB = bvA;
            if (jlB != jlA)
                bvB = *(const float2*)(BvBase + jlB * R_ + c * 2);
            float2 hA, hB;
            hA.x = t32(fmaxf(aiA.x + bvA.x, 0.f));
            hA.y = t32(fmaxf(aiA.y + bvA.y, 0.f));
            hB.x = t32(fmaxf(aiB.x + bvB.x, 0.f));
            hB.y = t32(fmaxf(aiB.y + bvB.y, 0.f));
            *(float2*)(base + OFF_H1A + q * 544 + c * 8) = hA;
            *(float2*)(base + OFF_H1B + q * 544 + c * 8) = hB;
        }
        __syncthreads();

        // ---- HMMA mainloop: 64q x 64n per warp, K=128 ----
        float d[4][8][4];
#pragma unroll
        for (int mt = 0; mt < 4; ++mt)
#pragma unroll
            for (int nt = 0; nt < 8; ++nt)
#pragma unroll
                for (int e = 0; e < 4; ++e) d[mt][nt][e] = 0.f;

#pragma unroll 2
        for (int ks = 0; ks < 16; ++ks) {
            uint2 aF[4][2];
#pragma unroll
            for (int mt = 0; mt < 4; ++mt) {
                aF[mt][0] = *(const uint2*)(pA0 + mt * 16 * 544 + ks * 32);
                aF[mt][1] = *(const uint2*)(pA0 + (mt * 16 + 8) * 544 + ks * 32);
            }
            uint2 bF[8];
#pragma unroll
            for (int nt = 0; nt < 8; ++nt)
                bF[nt] = *(const uint2*)(pB0 + ks * 4224 + nt * 64);
#pragma unroll
            for (int mt = 0; mt < 4; ++mt)
#pragma unroll
                for (int nt = 0; nt < 8; ++nt)
                    mma_tf32(d[mt][nt],
                             aF[mt][0].x, aF[mt][1].x, aF[mt][0].y, aF[mt][1].y,
                             bF[nt].x, bF[nt].y);
        }

        // ---- epilogue: relu(+b2) dot W3, quad shuffle, 2-warp reduce ----
        float p[8];
#pragma unroll
        for (int mt = 0; mt < 4; ++mt) {
            float s0 = 0.f, s1 = 0.f;
#pragma unroll
            for (int nt = 0; nt < 8; ++nt) {
                s0 += fmaxf(d[mt][nt][0] + b2v[nt][0], 0.f) * w3v[nt][0];
                s0 += fmaxf(d[mt][nt][1] + b2v[nt][1], 0.f) * w3v[nt][1];
                s1 += fmaxf(d[mt][nt][2] + b2v[nt][0], 0.f) * w3v[nt][0];
                s1 += fmaxf(d[mt][nt][3] + b2v[nt][1], 0.f) * w3v[nt][1];
            }
            p[mt * 2] = s0;
            p[mt * 2 + 1] = s1;
        }
#pragma unroll
        for (int v = 0; v < 8; ++v) {
            p[v] += __shfl_xor_sync(0xffffffffu, p[v], 1);
            p[v] += __shfl_xor_sync(0xffffffffu, p[v], 2);
        }
        {
            // lane (g,t) writes rows of m-tile mt = t within this warp's 64 rows
            int r0 = mq * 64 + t * 16 + g;
            sRed[r0 * 2 + nh] = p[t * 2];
            sRed[(r0 + 8) * 2 + nh] = p[t * 2 + 1];
        }
        __syncthreads();

        // ---- write out: 256 rows = 2 i-tiles x 128 q ----
        {
            int tile = tid >> 7;
            int q = tid & 127;
            int qg = qbase + q;
            if (qg < PAIRS) {
                float2 rr = *(const float2*)(sRed + tid * 2);
                out[(size_t)b * P_TOT + (size_t)(ia + tile) * PAIRS + qg] =
                    rr.x + rr.y + b3v;
            }
        }
        // next build's h1 writes are safe: every mainloop reader passed the
        // post-epilogue barrier above; sRed reads complete in-thread before
        // that thread writes h1, and other threads' sRed writes for macro m+1
        // occur only after the next build barrier.
    }
}

// ---------------------------------------------------------------------------
extern "C" void kernel_launch(void* const* d_in, const int* in_sizes, int n_in,
                              void* d_out, int out_size) {
    const float* feat = (const float*)d_in[0];
    const float* W1   = (const float*)d_in[1];
    const float* b1   = (const float*)d_in[2];
    const float* W2   = (const float*)d_in[3];
    const float* b2   = (const float*)d_in[4];
    const float* W3   = (const float*)d_in[5];
    const float* b3   = (const float*)d_in[6];
    float* out = (float*)d_out;

    prep_kernel<<<B_ * N_ + 8, 128>>>(feat, W1, b1, W2);

    cudaFuncSetAttribute(relnet_mma, cudaFuncAttributeMaxDynamicSharedMemorySize,
                         SMEM_BYTES);
    dim3 grid(4, N_ / GI, B_);
    relnet_mma<<<grid, 256, SMEM_BYTES>>>(b2, W3, b3, out);
}

// round 10
// speedup vs baseline: 3.0578x; 1.1022x over previous
#include <cuda_runtime.h>
#include <cstdint>

#define B_ 4
#define N_ 512
#define F_ 64
#define R_ 128
#define PAIRS 511                 // N-1
#define P_TOT (N_ * PAIRS)        // 261632
#define GI 8                      // i-values per CTA (4 macro pairs)

// Precomputed half-GEMMs in PAIR-PERMUTED column order:
// column r=ks*8+kk -> pos = ks*8 + (kk&3)*2 + (kk>>2)  ((k,k+4) adjacent float2)
__device__ float g_Abuf[B_ * N_ * R_];   // A = feat @ W1[:64] + b1
__device__ float g_Bbuf[B_ * N_ * R_];   // Bv = feat @ W1[64:]
// W2 tf32, fragment layout: W2p[(ks*4+t)][n] = (W2[ks*8+t][n], W2[ks*8+t+4][n]),
// row stride 132 float2.
__device__ float g_W2t[64 * 132 * 2];

__device__ __forceinline__ float t32(float x) {
    float r;
    asm("cvt.rna.tf32.f32 %0, %1;" : "=f"(r) : "f"(x));
    return r;
}

__device__ __forceinline__ void mma_tf32(float* d, uint32_t a0, uint32_t a1,
                                         uint32_t a2, uint32_t a3,
                                         uint32_t b0, uint32_t b1) {
    asm volatile(
        "mma.sync.aligned.m16n8k8.row.col.f32.tf32.tf32.f32 "
        "{%0,%1,%2,%3}, {%4,%5,%6,%7}, {%8,%9}, {%0,%1,%2,%3};"
        : "+f"(d[0]), "+f"(d[1]), "+f"(d[2]), "+f"(d[3])
        : "r"(a0), "r"(a1), "r"(a2), "r"(a3), "r"(b0), "r"(b1));
}

// ---------------------------------------------------------------------------
// Prep: blocks [0,2048) = half-projections; blocks [2048,2056) = W2 permute.
// ---------------------------------------------------------------------------
__global__ __launch_bounds__(128) void prep_kernel(
    const float* __restrict__ feat, const float* __restrict__ W1,
    const float* __restrict__ b1, const float* __restrict__ W2) {
    const int blk = blockIdx.x;
    if (blk < B_ * N_) {
        __shared__ float sf[F_];
        const int r = threadIdx.x;
        if (r < F_) sf[r] = feat[blk * F_ + r];
        __syncthreads();
        float a = b1[r];
        float bb = 0.f;
#pragma unroll 8
        for (int f = 0; f < F_; ++f) {
            float fv = sf[f];
            a  += fv * W1[f * R_ + r];
            bb += fv * W1[(F_ + f) * R_ + r];
        }
        int pos = (r & ~7) | ((r & 3) << 1) | ((r >> 2) & 1);
        g_Abuf[blk * R_ + pos] = a;
        g_Bbuf[blk * R_ + pos] = bb;
    } else {
        const int base = (blk - B_ * N_) * 2048 + threadIdx.x;
#pragma unroll
        for (int it = 0; it < 16; ++it) {
            int idx = base + it * 128;       // idx = k*128 + n
            int k = idx >> 7, n = idx & 127;
            float v = t32(W2[idx]);
            int ks = k >> 3, kk = k & 7, tq = kk & 3, hi = kk >> 2;
            g_W2t[((ks * 4 + tq) * 132 + n) * 2 + hi] = v;
        }
    }
}

// ---------------------------------------------------------------------------
// Main: HMMA tf32 fused pair-MLP, 256x128 macro-tile (2 i per pass).
// Grid (4 jt, 64 ig, 4 b), 512 threads = 16 warps (4 per SMSP).
// Warp w: mw = w&3 (64-row block of 256), nw = w>>2 (32-col quarter).
// SMEM: W2p 67584 | h1A 128x544 | h1B 128x544 | red 256x4 f32
// ---------------------------------------------------------------------------
#define OFF_W2 0
#define OFF_H1A 67584
#define OFF_H1B (67584 + 69632)          // 137216
#define OFF_RED (OFF_H1B + 69632)        // 206848
#define SMEM_BYTES (OFF_RED + 4096 + 64) // 211008

extern __shared__ char smem_raw[];

__global__ __launch_bounds__(512, 1)
void relnet_mma(const float* __restrict__ b2, const float* __restrict__ W3,
                const float* __restrict__ b3, float* __restrict__ out) {
    const int tid = threadIdx.x;
    const int warp = tid >> 5;
    const int lane = tid & 31;
    const int g = lane >> 2;            // groupID
    const int t = lane & 3;             // thread-in-group
    const int mw = warp & 3;            // 64-row block (0,1 -> tile A; 2,3 -> tile B)
    const int nw = warp >> 2;           // 32-col quarter
    const int jt = blockIdx.x;
    const int i0 = blockIdx.y * GI;
    const int b = blockIdx.z;
    const int qbase = jt * 128;
    const int j0 = jt * 128;

    char* base = smem_raw;
    float* sRed = (float*)(base + OFF_RED);

    // ---- stage W2p (already permuted + tf32 in gmem) ----
    {
        const float4* src = (const float4*)g_W2t;
        float4* dst = (float4*)(base + OFF_W2);
#pragma unroll
        for (int it = 0; it < 9; ++it) {
            int v = tid + it * 512;
            if (v < 4224) dst[v] = src[v];
        }
    }

    // ---- per-thread epilogue constants (32 n per warp) ----
    float b2v[4][2], w3v[4][2];
#pragma unroll
    for (int nt = 0; nt < 4; ++nt) {
        int n = nw * 32 + nt * 8 + 2 * t;
        b2v[nt][0] = b2[n];     b2v[nt][1] = b2[n + 1];
        w3v[nt][0] = W3[n];     w3v[nt][1] = W3[n + 1];
    }
    const float b3v = b3[0];

    // build-loop constants: 512 threads, c = col-pair 0..63, q0 = 0..7
    const int c = tid & 63;
    const int q0 = tid >> 6;
    const float* BvBase = g_Bbuf + ((size_t)b * N_ + j0) * R_;

    // mainloop base pointers
    const char* pA0 = base + (mw >= 2 ? OFF_H1B : OFF_H1A) +
                      ((mw & 1) * 64 + g) * 544 + t * 8;
    const char* pB0 = base + OFF_W2 + (t * 132 + nw * 32 + g) * 8;

    __syncthreads();   // W2p staged before first mainloop

    for (int m = 0; m < 4; ++m) {
        const int ia = i0 + 2 * m;
        const int ib = ia + 1;

        // ---- build h1A/h1B (relu(Ai + Bv_j), tf32); Bv straight from L2 ----
        float2 aiA = *(const float2*)(g_Abuf + ((size_t)b * N_ + ia) * R_ + c * 2);
        float2 aiB = *(const float2*)(g_Abuf + ((size_t)b * N_ + ib) * R_ + c * 2);
        char* hA = base + OFF_H1A + q0 * 544 + c * 8;
        char* hB = base + OFF_H1B + q0 * 544 + c * 8;
#pragma unroll 4
        for (int it = 0; it < 16; ++it) {
            int q = q0 + it * 8;
            int qg = qbase + q;
            int jlA = q + ((qg >= ia && qg <= PAIRS - 1) ? 1 : 0);
            int jlB = q + ((qg >= ib && qg <= PAIRS - 1) ? 1 : 0);
            float2 bvA = *(const float2*)(BvBase + jlA * R_ + c * 2);
            float2 bvB = bvA;
            if (jlB != jlA)
                bvB = *(const float2*)(BvBase + jlB * R_ + c * 2);
            float2 hAv, hBv;
            hAv.x = t32(fmaxf(aiA.x + bvA.x, 0.f));
            hAv.y = t32(fmaxf(aiA.y + bvA.y, 0.f));
            hBv.x = t32(fmaxf(aiB.x + bvB.x, 0.f));
            hBv.y = t32(fmaxf(aiB.y + bvB.y, 0.f));
            *(float2*)(hA + it * (8 * 544)) = hAv;
            *(float2*)(hB + it * (8 * 544)) = hBv;
        }
        __syncthreads();

        // ---- HMMA mainloop: 64q x 32n per warp, K=128 ----
        float d[4][4][4];
#pragma unroll
        for (int mt = 0; mt < 4; ++mt)
#pragma unroll
            for (int nt = 0; nt < 4; ++nt)
#pragma unroll
                for (int e = 0; e < 4; ++e) d[mt][nt][e] = 0.f;

#pragma unroll 4
        for (int ks = 0; ks < 16; ++ks) {
            uint2 aF[4][2];
#pragma unroll
            for (int mt = 0; mt < 4; ++mt) {
                aF[mt][0] = *(const uint2*)(pA0 + mt * 16 * 544 + ks * 32);
                aF[mt][1] = *(const uint2*)(pA0 + (mt * 16 + 8) * 544 + ks * 32);
            }
            uint2 bF[4];
#pragma unroll
            for (int nt = 0; nt < 4; ++nt)
                bF[nt] = *(const uint2*)(pB0 + ks * 4224 + nt * 64);
#pragma unroll
            for (int mt = 0; mt < 4; ++mt)
#pragma unroll
                for (int nt = 0; nt < 4; ++nt)
                    mma_tf32(d[mt][nt],
                             aF[mt][0].x, aF[mt][1].x, aF[mt][0].y, aF[mt][1].y,
                             bF[nt].x, bF[nt].y);
        }

        // ---- epilogue: relu(+b2) dot W3, quad shuffle, 4-warp reduce ----
        float p[8];
#pragma unroll
        for (int mt = 0; mt < 4; ++mt) {
            float s0 = 0.f, s1 = 0.f;
#pragma unroll
            for (int nt = 0; nt < 4; ++nt) {
                s0 += fmaxf(d[mt][nt][0] + b2v[nt][0], 0.f) * w3v[nt][0];
                s0 += fmaxf(d[mt][nt][1] + b2v[nt][1], 0.f) * w3v[nt][1];
                s1 += fmaxf(d[mt][nt][2] + b2v[nt][0], 0.f) * w3v[nt][0];
                s1 += fmaxf(d[mt][nt][3] + b2v[nt][1], 0.f) * w3v[nt][1];
            }
            p[mt * 2] = s0;
            p[mt * 2 + 1] = s1;
        }
#pragma unroll
        for (int v = 0; v < 8; ++v) {
            p[v] += __shfl_xor_sync(0xffffffffu, p[v], 1);
            p[v] += __shfl_xor_sync(0xffffffffu, p[v], 2);
        }
        {
            // lane (g,t) holds the full sum for m-tile mt = t; write its rows
            int r0 = mw * 64 + t * 16 + g;
            sRed[r0 * 4 + nw] = p[t * 2];
            sRed[(r0 + 8) * 4 + nw] = p[t * 2 + 1];
        }
        __syncthreads();

        // ---- write out: 256 rows = 2 i-tiles x 128 q ----
        if (tid < 256) {
            int tile = tid >> 7;
            int q = tid & 127;
            int qg = qbase + q;
            if (qg < PAIRS) {
                float4 rr = *(const float4*)(sRed + tid * 4);
                out[(size_t)b * P_TOT + (size_t)(ia + tile) * PAIRS + qg] =
                    rr.x + rr.y + rr.z + rr.w + b3v;
            }
        }
        // next build's h1 writes are safe: every mainloop reader passed the
        // post-epilogue barrier; sRed reads for macro m complete in-thread
        // before that thread writes h1(m+1), and all other threads' sRed
        // writes for m+1 are ordered behind the next build barrier.
    }
}

// ---------------------------------------------------------------------------
extern "C" void kernel_launch(void* const* d_in, const int* in_sizes, int n_in,
                              void* d_out, int out_size) {
    const float* feat = (const float*)d_in[0];
    const float* W1   = (const float*)d_in[1];
    const float* b1   = (const float*)d_in[2];
    const float* W2   = (const float*)d_in[3];
    const float* b2   = (const float*)d_in[4];
    const float* W3   = (const float*)d_in[5];
    const float* b3   = (const float*)d_in[6];
    float* out = (float*)d_out;

    prep_kernel<<<B_ * N_ + 8, 128>>>(feat, W1, b1, W2);

    cudaFuncSetAttribute(relnet_mma, cudaFuncAttributeMaxDynamicSharedMemorySize,
                         SMEM_BYTES);
    dim3 grid(4, N_ / GI, B_);
    relnet_mma<<<grid, 512, SMEM_BYTES>>>(b2, W3, b3, out);
}

// round 12
// speedup vs baseline: 4.5789x; 1.4974x over previous
#include <cuda_runtime.h>
#include <cuda_fp16.h>
#include <cstdint>

#define B_ 4
#define N_ 512
#define F_ 64
#define R_ 128
#define PAIRS 511                 // N-1
#define P_TOT (N_ * PAIRS)        // 261632
#define GI 8                      // i-values per CTA (4 macro pairs)

// Half-projections stored in fp16-FRAGMENT-PERMUTED order:
// feature r -> unit = (r>>4)*8 + perm((r>>1)&7), pos = unit*2 + (r&1),
// perm(j) = (j&3)*2 + (j>>2). So one float2 (unit) = features (2k,2k+1) and
// unit+1 = (2k+8,2k+9): an LDS.64 yields a0/a2 (or b0/b1) of m16n8k16.
__device__ float g_Abuf[B_ * N_ * R_];   // A = feat @ W1[:64] + b1
__device__ float g_Bbuf[B_ * N_ * R_];   // Bv = feat @ W1[64:]
// W2 as fp16x2 units, same per-16k permutation: g_W2h[n*64 + unit]
__device__ uint32_t g_W2h[R_ * 64];

__device__ __forceinline__ void mma_f16(float* d, uint32_t a0, uint32_t a1,
                                        uint32_t a2, uint32_t a3,
                                        uint32_t b0, uint32_t b1) {
    asm volatile(
        "mma.sync.aligned.m16n8k16.row.col.f32.f16.f16.f32 "
        "{%0,%1,%2,%3}, {%4,%5,%6,%7}, {%8,%9}, {%0,%1,%2,%3};"
        : "+f"(d[0]), "+f"(d[1]), "+f"(d[2]), "+f"(d[3])
        : "r"(a0), "r"(a1), "r"(a2), "r"(a3), "r"(b0), "r"(b1));
}

// ---------------------------------------------------------------------------
// Prep: blocks [0,2048) = half-projections; blocks [2048,2056) = W2 pack.
// ---------------------------------------------------------------------------
__global__ __launch_bounds__(128) void prep_kernel(
    const float* __restrict__ feat, const float* __restrict__ W1,
    const float* __restrict__ b1, const float* __restrict__ W2) {
    const int blk = blockIdx.x;
    if (blk < B_ * N_) {
        __shared__ float sf[F_];
        const int r = threadIdx.x;
        if (r < F_) sf[r] = feat[blk * F_ + r];
        __syncthreads();
        float a = b1[r];
        float bb = 0.f;
#pragma unroll 8
        for (int f = 0; f < F_; ++f) {
            float fv = sf[f];
            a  += fv * W1[f * R_ + r];
            bb += fv * W1[(F_ + f) * R_ + r];
        }
        int j = (r >> 1) & 7;
        int unit = ((r >> 4) << 3) + ((j & 3) * 2 + (j >> 2));
        int pos = unit * 2 + (r & 1);
        g_Abuf[blk * R_ + pos] = a;
        g_Bbuf[blk * R_ + pos] = bb;
    } else {
        // pack W2 -> fp16x2 units, permuted: 8192 u32 over 1024 threads
        const int w = (blk - B_ * N_) * 128 + threadIdx.x;   // 0..1023
#pragma unroll
        for (int it = 0; it < 8; ++it) {
            int uidx = w + it * 1024;       // n*64 + u
            int n = uidx >> 6, u = uidx & 63;
            int ks = u >> 3, p = u & 7;
            int j16 = (p >> 1) | ((p & 1) << 2);
            int k0 = ks * 16 + j16 * 2;
            __half2 h = __floats2half2_rn(W2[k0 * R_ + n], W2[(k0 + 1) * R_ + n]);
            g_W2h[uidx] = *(uint32_t*)&h;
        }
    }
}

// ---------------------------------------------------------------------------
// Main: fp16 HMMA fused pair-MLP, 256x128 macro-tile (2 i per pass).
// Grid (4 jt, 64 ig, 4 b), 512 threads = 16 warps (4 per SMSP).
// Warp w: mw = w&3 (64-row block of 256), nw = w>>2 (32-col quarter).
// SMEM: W2h 128x288 | h1A 128x288 | h1B 128x288 | Bv 129x512 | red 256x4 f32
// ---------------------------------------------------------------------------
#define OFF_W2 0
#define OFF_H1A 36864
#define OFF_H1B 73728
#define OFF_BV 110592
#define OFF_RED (OFF_BV + 66048)          // 176640
#define SMEM_BYTES (OFF_RED + 4096 + 64)  // 180800

extern __shared__ char smem_raw[];

__global__ __launch_bounds__(512, 1)
void relnet_mma(const float* __restrict__ b2, const float* __restrict__ W3,
                const float* __restrict__ b3, float* __restrict__ out) {
    const int tid = threadIdx.x;
    const int warp = tid >> 5;
    const int lane = tid & 31;
    const int g = lane >> 2;            // groupID
    const int t = lane & 3;             // thread-in-group
    const int mw = warp & 3;            // 64-row block (0,1 -> tile A; 2,3 -> tile B)
    const int nw = warp >> 2;           // 32-col quarter
    const int jt = blockIdx.x;
    const int i0 = blockIdx.y * GI;
    const int b = blockIdx.z;
    const int qbase = jt * 128;
    const int j0 = jt * 128;

    char* base = smem_raw;
    float* sBv = (float*)(base + OFF_BV);
    float* sRed = (float*)(base + OFF_RED);

    // ---- stage W2h: 8192 u32 -> padded rows (n stride 288B) ----
    {
#pragma unroll
        for (int it = 0; it < 16; ++it) {
            int v = tid + it * 512;
            int n = v >> 6, u = v & 63;
            *(uint32_t*)(base + OFF_W2 + n * 288 + u * 4) = g_W2h[v];
        }
    }
    // ---- stage Bv slab rows j0..j0+128 (129 rows, zero-pad OOB) ----
    {
        const float4* src = ((const float4*)g_Bbuf) + ((size_t)b * N_ + j0) * 32;
        float4* dst = (float4*)sBv;
        int limit = (N_ - j0 < 129 ? N_ - j0 : 129) * 32;
#pragma unroll
        for (int it = 0; it < 9; ++it) {
            int v = tid + it * 512;
            if (v < 129 * 32)
                dst[v] = (v < limit) ? src[v] : make_float4(0.f, 0.f, 0.f, 0.f);
        }
    }

    // ---- per-thread epilogue constants (32 n per warp) ----
    float b2v[4][2], w3v[4][2];
#pragma unroll
    for (int nt = 0; nt < 4; ++nt) {
        int n = nw * 32 + nt * 8 + 2 * t;
        b2v[nt][0] = b2[n];     b2v[nt][1] = b2[n + 1];
        w3v[nt][0] = W3[n];     w3v[nt][1] = W3[n + 1];
    }
    const float b3v = b3[0];

    // build-loop constants: c = unit 0..63, q0 = 0..7
    const int c = tid & 63;
    const int q0 = tid >> 6;

    // mainloop base pointers
    const char* pA0 = base + (mw >= 2 ? OFF_H1B : OFF_H1A) +
                      ((mw & 1) * 64 + g) * 288 + t * 8;
    const char* pB0 = base + OFF_W2 + (nw * 32 + g) * 288 + t * 8;

    __syncthreads();   // W2h + Bv staged

    for (int m = 0; m < 4; ++m) {
        const int ia = i0 + 2 * m;
        const int ib = ia + 1;

        // ---- build h1A/h1B = fp16(relu(Ai + Bv_j)); Bv from SMEM slab ----
        float2 aiA = *(const float2*)(g_Abuf + ((size_t)b * N_ + ia) * R_ + c * 2);
        float2 aiB = *(const float2*)(g_Abuf + ((size_t)b * N_ + ib) * R_ + c * 2);
        char* hA = base + OFF_H1A + q0 * 288 + c * 4;
        char* hB = base + OFF_H1B + q0 * 288 + c * 4;
#pragma unroll 4
        for (int it = 0; it < 16; ++it) {
            int q = q0 + it * 8;
            int qg = qbase + q;
            int jlA = q + ((qg >= ia && qg <= PAIRS - 1) ? 1 : 0);
            int jlB = q + ((qg >= ib && qg <= PAIRS - 1) ? 1 : 0);
            float2 bvA = *(const float2*)(sBv + jlA * R_ + c * 2);
            float2 bvB = bvA;
            if (jlB != jlA)
                bvB = *(const float2*)(sBv + jlB * R_ + c * 2);
            __half2 hAv = __floats2half2_rn(fmaxf(aiA.x + bvA.x, 0.f),
                                            fmaxf(aiA.y + bvA.y, 0.f));
            __half2 hBv = __floats2half2_rn(fmaxf(aiB.x + bvB.x, 0.f),
                                            fmaxf(aiB.y + bvB.y, 0.f));
            *(uint32_t*)(hA + it * (8 * 288)) = *(uint32_t*)&hAv;
            *(uint32_t*)(hB + it * (8 * 288)) = *(uint32_t*)&hBv;
        }
        __syncthreads();

        // ---- HMMA fp16 mainloop: 64q x 32n per warp, K=128 (8 k-steps) ----
        float d[4][4][4];
#pragma unroll
        for (int mt = 0; mt < 4; ++mt)
#pragma unroll
            for (int nt = 0; nt < 4; ++nt)
#pragma unroll
                for (int e = 0; e < 4; ++e) d[mt][nt][e] = 0.f;

#pragma unroll
        for (int ks = 0; ks < 8; ++ks) {
            uint2 aF[4][2];
#pragma unroll
            for (int mt = 0; mt < 4; ++mt) {
                aF[mt][0] = *(const uint2*)(pA0 + mt * 16 * 288 + ks * 32);
                aF[mt][1] = *(const uint2*)(pA0 + (mt * 16 + 8) * 288 + ks * 32);
            }
            uint2 bF[4];
#pragma unroll
            for (int nt = 0; nt < 4; ++nt)
                bF[nt] = *(const uint2*)(pB0 + nt * 8 * 288 + ks * 32);
#pragma unroll
            for (int mt = 0; mt < 4; ++mt)
#pragma unroll
                for (int nt = 0; nt < 4; ++nt)
                    mma_f16(d[mt][nt],
                            aF[mt][0].x, aF[mt][1].x, aF[mt][0].y, aF[mt][1].y,
                            bF[nt].x, bF[nt].y);
        }

        // ---- epilogue: relu(+b2) dot W3, quad shuffle, 4-warp reduce ----
        float p[8];
#pragma unroll
        for (int mt = 0; mt < 4; ++mt) {
            float s0 = 0.f, s1 = 0.f;
#pragma unroll
            for (int nt = 0; nt < 4; ++nt) {
                s0 += fmaxf(d[mt][nt][0] + b2v[nt][0], 0.f) * w3v[nt][0];
                s0 += fmaxf(d[mt][nt][1] + b2v[nt][1], 0.f) * w3v[nt][1];
                s1 += fmaxf(d[mt][nt][2] + b2v[nt][0], 0.f) * w3v[nt][0];
                s1 += fmaxf(d[mt][nt][3] + b2v[nt][1], 0.f) * w3v[nt][1];
            }
            p[mt * 2] = s0;
            p[mt * 2 + 1] = s1;
        }
#pragma unroll
        for (int v = 0; v < 8; ++v) {
            p[v] += __shfl_xor_sync(0xffffffffu, p[v], 1);
            p[v] += __shfl_xor_sync(0xffffffffu, p[v], 2);
        }
        {
            // lane (g,t) holds the full sum for m-tile mt = t; write its rows
            int r0 = mw * 64 + t * 16 + g;
            sRed[r0 * 4 + nw] = p[t * 2];
            sRed[(r0 + 8) * 4 + nw] = p[t * 2 + 1];
        }
        __syncthreads();

        // ---- write out: 256 rows = 2 i-tiles x 128 q ----
        if (tid < 256) {
            int tile = tid >> 7;
            int q = tid & 127;
            int qg = qbase + q;
            if (qg < PAIRS) {
                float4 rr = *(const float4*)(sRed + tid * 4);
                out[(size_t)b * P_TOT + (size_t)(ia + tile) * PAIRS + qg] =
                    rr.x + rr.y + rr.z + rr.w + b3v;
            }
        }
        // safe: every h1/sRed reader passed the post-epilogue barrier before
        // the next macro's build writes begin (ordered by next build barrier).
    }
}

// ---------------------------------------------------------------------------
extern "C" void kernel_launch(void* const* d_in, const int* in_sizes, int n_in,
                              void* d_out, int out_size) {
    const float* feat = (const float*)d_in[0];
    const float* W1   = (const float*)d_in[1];
    const float* b1   = (const float*)d_in[2];
    const float* W2   = (const float*)d_in[3];
    const float* b2   = (const float*)d_in[4];
    const float* W3   = (const float*)d_in[5];
    const float* b3   = (const float*)d_in[6];
    float* out = (float*)d_out;

    prep_kernel<<<B_ * N_ + 8, 128>>>(feat, W1, b1, W2);

    cudaFuncSetAttribute(relnet_mma, cudaFuncAttributeMaxDynamicSharedMemorySize,
                         SMEM_BYTES);
    dim3 grid(4, N_ / GI, B_);
    relnet_mma<<<grid, 512, SMEM_BYTES>>>(b2, W3, b3, out);
}

// round 14
// speedup vs baseline: 5.0524x; 1.1034x over previous
#include <cuda_runtime.h>
#include <cuda_fp16.h>
#include <cstdint>

#define B_ 4
#define N_ 512
#define F_ 64
#define R_ 128
#define PAIRS 511                 // N-1
#define P_TOT (N_ * PAIRS)        // 261632
#define GI 8                      // i-values per CTA (1 per macro pass)

// Half-projections, BUILD-PERMUTED per 16-feature group:
// f = ks*16 + kk, kk = 2t + 8h + e  ->  pos = ks*16 + t*4 + h*2 + e
// so one float4 at (row, ks*16 + 4t) = features (2t, 2t+1, 2t+8, 2t+9):
// exactly the 4 fp32 feeding one thread's A-fragment k-slice.
__device__ float4 g_Abuf4[B_ * N_ * 32];   // A = feat @ W1[:64] + b1
__device__ float4 g_Bbuf4[B_ * N_ * 32];   // Bv = feat @ W1[64:]
// W2 packed fp16x2 in chunk layout: chunk(ks, np) = 512B, lane l=(g*4+t):
//   u32[0] = col 16np+g,   k (2t,2t+1)   (b0 of ntl=0)
//   u32[1] = col 16np+g,   k (2t+8,2t+9) (b1 of ntl=0)
//   u32[2] = col 16np+8+g, k (2t,2t+1)   (b0 of ntl=1)
//   u32[3] = col 16np+8+g, k (2t+8,2t+9) (b1 of ntl=1)
__device__ uint4 g_W2c[2048];

__device__ __forceinline__ void mma_f16(float* d, uint32_t a0, uint32_t a1,
                                        uint32_t a2, uint32_t a3,
                                        uint32_t b0, uint32_t b1) {
    asm volatile(
        "mma.sync.aligned.m16n8k16.row.col.f32.f16.f16.f32 "
        "{%0,%1,%2,%3}, {%4,%5,%6,%7}, {%8,%9}, {%0,%1,%2,%3};"
        : "+f"(d[0]), "+f"(d[1]), "+f"(d[2]), "+f"(d[3])
        : "r"(a0), "r"(a1), "r"(a2), "r"(a3), "r"(b0), "r"(b1));
}

// ---------------------------------------------------------------------------
// Prep: blocks [0,2048) = half-projections; blocks [2048,2056) = W2 pack.
// ---------------------------------------------------------------------------
__global__ __launch_bounds__(128) void prep_kernel(
    const float* __restrict__ feat, const float* __restrict__ W1,
    const float* __restrict__ b1, const float* __restrict__ W2) {
    const int blk = blockIdx.x;
    if (blk < B_ * N_) {
        __shared__ float sf[F_];
        const int r = threadIdx.x;
        if (r < F_) sf[r] = feat[blk * F_ + r];
        __syncthreads();
        float a = b1[r];
        float bb = 0.f;
#pragma unroll 8
        for (int f = 0; f < F_; ++f) {
            float fv = sf[f];
            a  += fv * W1[f * R_ + r];
            bb += fv * W1[(F_ + f) * R_ + r];
        }
        int pos = (r & ~15) | (((r >> 1) & 3) << 2) | (((r >> 3) & 1) << 1) | (r & 1);
        ((float*)g_Abuf4)[blk * R_ + pos] = a;
        ((float*)g_Bbuf4)[blk * R_ + pos] = bb;
    } else {
        const int w = (blk - B_ * N_) * 128 + threadIdx.x;   // 0..1023
#pragma unroll
        for (int it = 0; it < 8; ++it) {
            int uidx = w + it * 1024;           // 0..8191
            int idx = uidx & 3;
            int lane = (uidx >> 2) & 31;
            int np = (uidx >> 7) & 7;
            int ks = uidx >> 10;
            int g = lane >> 2, t = lane & 3;
            int k0 = ks * 16 + 2 * t + (idx & 1) * 8;
            int n = np * 16 + ((idx >> 1) & 1) * 8 + g;
            __half2 h = __floats2half2_rn(W2[k0 * R_ + n], W2[(k0 + 1) * R_ + n]);
            ((uint32_t*)g_W2c)[uidx] = *(uint32_t*)&h;
        }
    }
}

// ---------------------------------------------------------------------------
// Main: fp16 HMMA fused pair-MLP, 128x128 tile per macro, 2 CTAs/SM.
// Grid (4 jt, 64 ig, 4 b), 256 threads = 8 warps: mw = w&1 (64-row half),
// nw = w>>1 (32-col quarter). Warp tile 64x32.
// SMEM: h1 chunks 32K | W2 chunks 32K | red 2K | b2 512 | w3 512 = 68608 B
// h1 chunk (Q=0..7, ks=0..7) = 512B at (Q*8+ks)*512; lane 16B = full A frag.
// ---------------------------------------------------------------------------
#define OFF_H1 0
#define OFF_W2 32768
#define OFF_RED 65536
#define OFF_B2 67584
#define OFF_W3 68096
#define SMEM_BYTES 68608

extern __shared__ char smem_raw[];

__global__ __launch_bounds__(256, 2)
void relnet_mma(const float* __restrict__ b2, const float* __restrict__ W3,
                const float* __restrict__ b3, float* __restrict__ out) {
    const int tid = threadIdx.x;
    const int warp = tid >> 5;
    const int lane = tid & 31;
    const int g = lane >> 2;
    const int t = lane & 3;
    const int mw = warp & 1;
    const int nw = warp >> 1;
    const int jt = blockIdx.x;
    const int i0 = blockIdx.y * GI;
    const int b = blockIdx.z;
    const int qbase = jt * 128;

    char* base = smem_raw;
    float* sRed = (float*)(base + OFF_RED);
    float* sB2 = (float*)(base + OFF_B2);
    float* sW3 = (float*)(base + OFF_W3);

    // ---- stage W2 chunks (already packed in gmem) ----
    {
        uint4* dst = (uint4*)(base + OFF_W2);
#pragma unroll
        for (int it = 0; it < 8; ++it) dst[tid + it * 256] = g_W2c[tid + it * 256];
    }
    if (tid < 128) { sB2[tid] = b2[tid]; sW3[tid] = W3[tid]; }
    const float b3v = b3[0];

    // build constants: warp w builds Q=w chunks; lane covers rows 16w+g, +8
    const int r1 = 16 * warp + g;
    const int r2 = r1 + 8;
    const int qg1 = qbase + r1;
    const int qg2 = qbase + r2;
    char* h1w = base + OFF_H1 + (warp * 8) * 512 + lane * 16;

    // mainloop base pointers (chunked, conflict-free LDS.128)
    const char* pA = base + OFF_H1 + mw * 16384 + lane * 16;  // +mt*4096 +ks*512
    const char* pB = base + OFF_W2 + (nw * 2) * 512 + lane * 16; // +ks*4096 +nb*512

    for (int m = 0; m < GI; ++m) {
        const int i = i0 + m;

        // ---- build h1 chunks: relu(A_i + Bv_j) -> fp16 fragments ----
        {
            int jl1 = r1 + ((qg1 >= i && qg1 < PAIRS) ? 1 : 0);
            int jl2 = r2 + ((qg2 >= i && qg2 < PAIRS) ? 1 : 0);
            const float4* Ar = g_Abuf4 + (size_t)(b * N_ + i) * 32 + t;
            const float4* B1 = g_Bbuf4 + (size_t)(b * N_ + qbase + jl1) * 32 + t;
            const float4* B2r = g_Bbuf4 + (size_t)(b * N_ + qbase + jl2) * 32 + t;
#pragma unroll
            for (int ks = 0; ks < 8; ++ks) {
                float4 av = Ar[ks * 4];
                float4 v1 = B1[ks * 4];
                float4 v2 = B2r[ks * 4];
                __half2 p0 = __floats2half2_rn(fmaxf(av.x + v1.x, 0.f),
                                               fmaxf(av.y + v1.y, 0.f));
                __half2 p1 = __floats2half2_rn(fmaxf(av.z + v1.z, 0.f),
                                               fmaxf(av.w + v1.w, 0.f));
                __half2 p2 = __floats2half2_rn(fmaxf(av.x + v2.x, 0.f),
                                               fmaxf(av.y + v2.y, 0.f));
                __half2 p3 = __floats2half2_rn(fmaxf(av.z + v2.z, 0.f),
                                               fmaxf(av.w + v2.w, 0.f));
                uint4 val;
                val.x = *(uint32_t*)&p0;   // row1, k(2t,2t+1)   = a0
                val.y = *(uint32_t*)&p1;   // row1, k(2t+8,2t+9) = a2
                val.z = *(uint32_t*)&p2;   // row2, k(2t,2t+1)   = a1
                val.w = *(uint32_t*)&p3;   // row2, k(2t+8,2t+9) = a3
                *(uint4*)(h1w + ks * 512) = val;
            }
        }
        __syncthreads();   // h1 (and, on m==0, W2/b2/w3) visible to all

        // ---- HMMA mainloop: 64q x 32n per warp, K=128, LDS.128 frags ----
        float d[4][2][2][4];
#pragma unroll
        for (int mt = 0; mt < 4; ++mt)
#pragma unroll
            for (int nb = 0; nb < 2; ++nb)
#pragma unroll
                for (int nl = 0; nl < 2; ++nl)
#pragma unroll
                    for (int e = 0; e < 4; ++e) d[mt][nb][nl][e] = 0.f;

#pragma unroll
        for (int ks = 0; ks < 8; ++ks) {
            uint4 a[4];
#pragma unroll
            for (int mt = 0; mt < 4; ++mt)
                a[mt] = *(const uint4*)(pA + mt * 4096 + ks * 512);
            uint4 bb[2];
#pragma unroll
            for (int nb = 0; nb < 2; ++nb)
                bb[nb] = *(const uint4*)(pB + ks * 4096 + nb * 512);
#pragma unroll
            for (int mt = 0; mt < 4; ++mt)
#pragma unroll
                for (int nb = 0; nb < 2; ++nb) {
                    mma_f16(d[mt][nb][0], a[mt].x, a[mt].z, a[mt].y, a[mt].w,
                            bb[nb].x, bb[nb].y);
                    mma_f16(d[mt][nb][1], a[mt].x, a[mt].z, a[mt].y, a[mt].w,
                            bb[nb].z, bb[nb].w);
                }
        }

        // ---- epilogue: relu(+b2) dot W3, quad shuffle, 4-warp reduce ----
        float p0[4], p1[4];
        float2 bw[2][2], ww[2][2];
#pragma unroll
        for (int nb = 0; nb < 2; ++nb)
#pragma unroll
            for (int nl = 0; nl < 2; ++nl) {
                int n = nw * 32 + nb * 16 + nl * 8 + 2 * t;
                bw[nb][nl] = *(const float2*)(sB2 + n);
                ww[nb][nl] = *(const float2*)(sW3 + n);
            }
#pragma unroll
        for (int mt = 0; mt < 4; ++mt) {
            float s0 = 0.f, s1 = 0.f;
#pragma unroll
            for (int nb = 0; nb < 2; ++nb)
#pragma unroll
                for (int nl = 0; nl < 2; ++nl) {
                    const float* dd = d[mt][nb][nl];
                    s0 += fmaxf(dd[0] + bw[nb][nl].x, 0.f) * ww[nb][nl].x;
                    s0 += fmaxf(dd[1] + bw[nb][nl].y, 0.f) * ww[nb][nl].y;
                    s1 += fmaxf(dd[2] + bw[nb][nl].x, 0.f) * ww[nb][nl].x;
                    s1 += fmaxf(dd[3] + bw[nb][nl].y, 0.f) * ww[nb][nl].y;
                }
            p0[mt] = s0;
            p1[mt] = s1;
        }
#pragma unroll
        for (int v = 0; v < 4; ++v) {
            p0[v] += __shfl_xor_sync(0xffffffffu, p0[v], 1);
            p0[v] += __shfl_xor_sync(0xffffffffu, p0[v], 2);
            p1[v] += __shfl_xor_sync(0xffffffffu, p1[v], 1);
            p1[v] += __shfl_xor_sync(0xffffffffu, p1[v], 2);
        }
        {
            // lane (g,t) emits m-tile mt = t (all quad lanes hold full sums)
            float v0 = (t == 0) ? p0[0] : (t == 1) ? p0[1] : (t == 2) ? p0[2] : p0[3];
            float v1 = (t == 0) ? p1[0] : (t == 1) ? p1[1] : (t == 2) ? p1[2] : p1[3];
            int r0 = mw * 64 + t * 16 + g;
            sRed[r0 * 4 + nw] = v0;
            sRed[(r0 + 8) * 4 + nw] = v1;
        }
        __syncthreads();

        if (tid < 128) {
            int qg = qbase + tid;
            if (qg < PAIRS) {
                float4 rr = *(const float4*)(sRed + tid * 4);
                out[(size_t)b * P_TOT + (size_t)i * PAIRS + qg] =
                    rr.x + rr.y + rr.z + rr.w + b3v;
            }
        }
        // next macro's build (h1) is separated from this macro's h1 readers
        // by the barrier above; sRed rewrite is behind the next build barrier.
    }
}

// ---------------------------------------------------------------------------
extern "C" void kernel_launch(void* const* d_in, const int* in_sizes, int n_in,
                              void* d_out, int out_size) {
    const float* feat = (const float*)d_in[0];
    const float* W1   = (const float*)d_in[1];
    const float* b1   = (const float*)d_in[2];
    const float* W2   = (const float*)d_in[3];
    const float* b2   = (const float*)d_in[4];
    const float* W3   = (const float*)d_in[5];
    const float* b3   = (const float*)d_in[6];
    float* out = (float*)d_out;

    prep_kernel<<<B_ * N_ + 8, 128>>>(feat, W1, b1, W2);

    cudaFuncSetAttribute(relnet_mma, cudaFuncAttributeMaxDynamicSharedMemorySize,
                         SMEM_BYTES);
    dim3 grid(4, N_ / GI, B_);
    relnet_mma<<<grid, 256, SMEM_BYTES>>>(b2, W3, b3, out);
}